// round 1
// baseline (speedup 1.0000x reference)
#include <cuda_runtime.h>
#include <math.h>

#define BB 4
#define CC 256
#define HH 64
#define WW 64
#define HW 4096
#define CK 2304   /* C * 9 */
#define CPG 8     /* channels per group (256/32) */

// ---------------- scratch (device globals; no allocations) ----------------
__device__ float g_h  [(size_t)BB*CC*HW];   // relu(gn(.))
__device__ float g_f  [(size_t)BB*CC*HW];   // depthwise out
__device__ float g_off[(size_t)BB*18*HW];   // offsets
__device__ float g_col[(size_t)BB*CK*HW];   // im2col (151MB)
__device__ float g_h2 [(size_t)BB*CC*HW];   // deform conv1 out

// ---------------- GroupNorm + ReLU ----------------
// grid = B*32 blocks (one per (b,group)), 256 threads
__global__ void gn_relu_kernel(const float* __restrict__ in,
                               const float* __restrict__ gamma,
                               const float* __restrict__ beta,
                               float* __restrict__ out) {
    int b = blockIdx.x >> 5, g = blockIdx.x & 31;
    size_t base = ((size_t)b*CC + g*CPG) * HW;
    const float4* p4 = (const float4*)(in + base);
    const int N4 = CPG*HW/4; // 8192
    float s = 0.f, s2 = 0.f;
    for (int i = threadIdx.x; i < N4; i += 256) {
        float4 v = p4[i];
        s  += v.x + v.y + v.z + v.w;
        s2 += v.x*v.x + v.y*v.y + v.z*v.z + v.w*v.w;
    }
    #pragma unroll
    for (int o = 16; o; o >>= 1) {
        s  += __shfl_xor_sync(0xffffffffu, s,  o);
        s2 += __shfl_xor_sync(0xffffffffu, s2, o);
    }
    __shared__ float sh[16];
    __shared__ float stats[2];
    int wid = threadIdx.x >> 5, lane = threadIdx.x & 31;
    if (lane == 0) { sh[wid] = s; sh[8 + wid] = s2; }
    __syncthreads();
    if (threadIdx.x == 0) {
        float ts = 0.f, ts2 = 0.f;
        #pragma unroll
        for (int i = 0; i < 8; i++) { ts += sh[i]; ts2 += sh[8+i]; }
        const float invN = 1.f / (float)(CPG*HW);
        float mean = ts * invN;
        float var  = ts2 * invN - mean*mean;
        stats[0] = mean;
        stats[1] = rsqrtf(var + 1e-5f);
    }
    __syncthreads();
    float mean = stats[0], inv = stats[1];
    float4* o4 = (float4*)(out + base);
    for (int i = threadIdx.x; i < N4; i += 256) {
        int c = g*CPG + (i >> 10);              // 1024 float4 per channel
        float ga = gamma[c] * inv;
        float be = beta[c] - mean * ga;
        float4 v = p4[i];
        v.x = fmaxf(fmaf(v.x, ga, be), 0.f);
        v.y = fmaxf(fmaf(v.y, ga, be), 0.f);
        v.z = fmaxf(fmaf(v.z, ga, be), 0.f);
        v.w = fmaxf(fmaf(v.w, ga, be), 0.f);
        o4[i] = v;
    }
}

// ---------------- Depthwise 7x7 SAME ----------------
// grid = B*C blocks (one 64x64 plane each), 256 threads
__global__ void dw_conv_kernel(const float* __restrict__ in,
                               const float* __restrict__ wts,
                               float* __restrict__ out) {
    int bc = blockIdx.x;
    int c = bc & (CC - 1);
    const float* p = in + (size_t)bc * HW;
    __shared__ float tile[70*70];
    __shared__ float wk[49];
    if (threadIdx.x < 49) wk[threadIdx.x] = wts[c*49 + threadIdx.x];
    for (int i = threadIdx.x; i < 70*70; i += 256) {
        int ty = i / 70 - 3, tx = i % 70 - 3;
        tile[i] = (ty >= 0 && ty < 64 && tx >= 0 && tx < 64) ? p[ty*64 + tx] : 0.f;
    }
    __syncthreads();
    int xg = (threadIdx.x & 15) * 4;
    int yb = threadIdx.x >> 4;
    #pragma unroll
    for (int it = 0; it < 4; it++) {
        int oy = it*16 + yb;
        float a0 = 0.f, a1 = 0.f, a2 = 0.f, a3 = 0.f;
        #pragma unroll
        for (int dy = 0; dy < 7; dy++) {
            const float* r = &tile[(oy+dy)*70 + xg];
            #pragma unroll
            for (int dx = 0; dx < 7; dx++) {
                float wv = wk[dy*7 + dx];
                a0 = fmaf(r[dx+0], wv, a0);
                a1 = fmaf(r[dx+1], wv, a1);
                a2 = fmaf(r[dx+2], wv, a2);
                a3 = fmaf(r[dx+3], wv, a3);
            }
        }
        float4 o4 = make_float4(a0, a1, a2, a3);
        *(float4*)&out[(size_t)bc*HW + oy*64 + xg] = o4;
    }
}

// ---------------- Pointwise 1x1 (18 outputs) + bias ----------------
// grid = B * (HW/256) = 64 blocks, 256 threads
__global__ void pw_kernel(const float* __restrict__ f,
                          const float* __restrict__ pw,
                          const float* __restrict__ pwb,
                          float* __restrict__ off) {
    int b = blockIdx.x >> 4;
    int p = (blockIdx.x & 15) * 256 + threadIdx.x;
    __shared__ float wsh[18*256];
    for (int i = threadIdx.x; i < 18*256; i += 256) wsh[i] = pw[i];
    __syncthreads();
    float acc[18];
    #pragma unroll
    for (int o = 0; o < 18; o++) acc[o] = 0.f;
    const float* fb = f + (size_t)b*CC*HW + p;
    for (int c = 0; c < CC; c++) {
        float v = fb[(size_t)c*HW];
        #pragma unroll
        for (int o = 0; o < 18; o++) acc[o] = fmaf(v, wsh[o*256 + c], acc[o]);
    }
    #pragma unroll
    for (int o = 0; o < 18; o++)
        off[((size_t)b*18 + o)*HW + p] = acc[o] + pwb[o];
}

// ---------------- im2col with bilinear deformable sampling ----------------
// grid = B*9*(HW/256) = 576 blocks, 256 threads
// col layout: [B][c*9+k][HW] so that w.reshape(O, C*9) multiplies directly
__global__ void im2col_kernel(const float* __restrict__ x,
                              const float* __restrict__ off,
                              float* __restrict__ col) {
    int blk = blockIdx.x;
    int pc = blk & 15;
    int k  = (blk >> 4) % 9;
    int b  = blk / 144;
    int p  = pc*256 + threadIdx.x;
    int yi = p >> 6, xi = p & 63;

    float offy = off[((size_t)b*18 + 2*k    )*HW + p];
    float offx = off[((size_t)b*18 + 2*k + 1)*HW + p];
    float py = (float)yi + (float)(k/3 - 1) + offy;
    float px = (float)xi + (float)(k%3 - 1) + offx;
    float y0f = floorf(py), x0f = floorf(px);
    float wy1 = py - y0f, wx1 = px - x0f;
    float wy0 = 1.f - wy1, wx0 = 1.f - wx1;
    float y1f = y0f + 1.f, x1f = x0f + 1.f;
    bool vy0 = (y0f >= 0.f) && (y0f <= 63.f);
    bool vy1 = (y1f >= 0.f) && (y1f <= 63.f);
    bool vx0 = (x0f >= 0.f) && (x0f <= 63.f);
    bool vx1 = (x1f >= 0.f) && (x1f <= 63.f);
    float w00 = (vy0 && vx0) ? wy0*wx0 : 0.f;
    float w01 = (vy0 && vx1) ? wy0*wx1 : 0.f;
    float w10 = (vy1 && vx0) ? wy1*wx0 : 0.f;
    float w11 = (vy1 && vx1) ? wy1*wx1 : 0.f;
    int yc0 = min(max((int)y0f, 0), 63);
    int yc1 = min(max((int)y1f, 0), 63);
    int xc0 = min(max((int)x0f, 0), 63);
    int xc1 = min(max((int)x1f, 0), 63);
    int i00 = yc0*64 + xc0, i01 = yc0*64 + xc1;
    int i10 = yc1*64 + xc0, i11 = yc1*64 + xc1;

    const float* xb = x + (size_t)b*CC*HW;
    float* cp = col + ((size_t)b*CK + k)*HW + p;
    #pragma unroll 4
    for (int c = 0; c < CC; c++) {
        const float* pl = xb + (size_t)c*HW;
        float v = w00*pl[i00];
        v = fmaf(w01, pl[i01], v);
        v = fmaf(w10, pl[i10], v);
        v = fmaf(w11, pl[i11], v);
        cp[(size_t)c*9*HW] = v;
    }
}

// ---------------- SGEMM: C[b,o,p] = sum_ck A[o,ck]*col[b,ck,p] + bias (+res) ----------------
// BM=128, BN=64, BK=8, 256 threads, 8x4 per-thread tile, double buffered
template<int ADD_RES>
__global__ void __launch_bounds__(256) gemm_kernel(
        const float* __restrict__ A,     // [256][2304]
        const float* __restrict__ Bm,    // [B][2304][HW]
        const float* __restrict__ bias,  // [256]
        const float* __restrict__ res,   // [B][256][HW] or null
        float* __restrict__ Cm) {        // [B][256][HW]
    __shared__ float As[2][8][128];
    __shared__ float Bs[2][8][64];
    int tid = threadIdx.x;
    int bn = blockIdx.x * 64;
    int bm = blockIdx.y * 128;
    int b  = blockIdx.z;
    const float* Bp = Bm + (size_t)b*CK*HW;

    int arow = tid >> 1,  acol = (tid & 1) * 4;
    int brow = tid >> 4,  bcol = (tid & 15) * 4;   // only tid<128 loads B
    int tm = tid >> 4,    tn = tid & 15;

    float acc[8][4];
    #pragma unroll
    for (int i = 0; i < 8; i++)
        #pragma unroll
        for (int j = 0; j < 4; j++) acc[i][j] = 0.f;

    const float* aptr = A + (size_t)(bm + arow)*CK + acol;
    const float* bptr = Bp + (size_t)brow*HW + bn + bcol;

    float4 areg = *(const float4*)aptr;
    float4 breg = make_float4(0.f, 0.f, 0.f, 0.f);
    if (tid < 128) breg = *(const float4*)bptr;

    As[0][acol+0][arow] = areg.x;
    As[0][acol+1][arow] = areg.y;
    As[0][acol+2][arow] = areg.z;
    As[0][acol+3][arow] = areg.w;
    if (tid < 128) *(float4*)&Bs[0][brow][bcol] = breg;
    __syncthreads();

    const int NKT = CK / 8;  // 288
    for (int kt = 0; kt < NKT; kt++) {
        int buf = kt & 1;
        if (kt + 1 < NKT) {
            areg = *(const float4*)(aptr + (kt+1)*8);
            if (tid < 128) breg = *(const float4*)(bptr + (size_t)(kt+1)*8*HW);
        }
        #pragma unroll
        for (int kk = 0; kk < 8; kk++) {
            float4 a0 = *(const float4*)&As[buf][kk][tm*8];
            float4 a1 = *(const float4*)&As[buf][kk][tm*8 + 4];
            float4 bv = *(const float4*)&Bs[buf][kk][tn*4];
            float am[8] = {a0.x, a0.y, a0.z, a0.w, a1.x, a1.y, a1.z, a1.w};
            float bb4[4] = {bv.x, bv.y, bv.z, bv.w};
            #pragma unroll
            for (int i = 0; i < 8; i++)
                #pragma unroll
                for (int j = 0; j < 4; j++)
                    acc[i][j] = fmaf(am[i], bb4[j], acc[i][j]);
        }
        __syncthreads();
        if (kt + 1 < NKT) {
            int nb = buf ^ 1;
            As[nb][acol+0][arow] = areg.x;
            As[nb][acol+1][arow] = areg.y;
            As[nb][acol+2][arow] = areg.z;
            As[nb][acol+3][arow] = areg.w;
            if (tid < 128) *(float4*)&Bs[nb][brow][bcol] = breg;
            __syncthreads();
        }
    }

    #pragma unroll
    for (int i = 0; i < 8; i++) {
        int row = bm + tm*8 + i;
        size_t o = ((size_t)b*CC + row)*HW + bn + tn*4;
        float bs = bias[row];
        float4 v = make_float4(acc[i][0]+bs, acc[i][1]+bs, acc[i][2]+bs, acc[i][3]+bs);
        if (ADD_RES) {
            float4 r = *(const float4*)&res[o];
            v.x += r.x; v.y += r.y; v.z += r.z; v.w += r.w;
        }
        *(float4*)&Cm[o] = v;
    }
}

// ---------------- launch ----------------
extern "C" void kernel_launch(void* const* d_in, const int* in_sizes, int n_in,
                              void* d_out, int out_size) {
    const float* x    = (const float*)d_in[0];
    const float* gn1g = (const float*)d_in[1];
    const float* gn1b = (const float*)d_in[2];
    const float* dw1  = (const float*)d_in[3];
    const float* pw1  = (const float*)d_in[4];
    const float* pwb1 = (const float*)d_in[5];
    const float* w1   = (const float*)d_in[6];
    const float* b1   = (const float*)d_in[7];
    const float* gn2g = (const float*)d_in[8];
    const float* gn2b = (const float*)d_in[9];
    const float* dw2  = (const float*)d_in[10];
    const float* pw2  = (const float*)d_in[11];
    const float* pwb2 = (const float*)d_in[12];
    const float* w2   = (const float*)d_in[13];
    const float* b2   = (const float*)d_in[14];
    float* out = (float*)d_out;

    float *h, *f, *off, *col, *h2;
    cudaGetSymbolAddress((void**)&h,   g_h);
    cudaGetSymbolAddress((void**)&f,   g_f);
    cudaGetSymbolAddress((void**)&off, g_off);
    cudaGetSymbolAddress((void**)&col, g_col);
    cudaGetSymbolAddress((void**)&h2,  g_h2);

    // stage 1
    gn_relu_kernel<<<128, 256>>>(x, gn1g, gn1b, h);
    dw_conv_kernel<<<BB*CC, 256>>>(h, dw1, f);
    pw_kernel<<<64, 256>>>(f, pw1, pwb1, off);
    im2col_kernel<<<576, 256>>>(h, off, col);
    gemm_kernel<0><<<dim3(64, 2, BB), 256>>>(w1, col, b1, nullptr, h2);

    // stage 2
    gn_relu_kernel<<<128, 256>>>(h2, gn2g, gn2b, h);
    dw_conv_kernel<<<BB*CC, 256>>>(h, dw2, f);
    pw_kernel<<<64, 256>>>(f, pw2, pwb2, off);
    im2col_kernel<<<576, 256>>>(h, off, col);
    gemm_kernel<1><<<dim3(64, 2, BB), 256>>>(w2, col, b2, x, out);
}

// round 7
// speedup vs baseline: 1.4633x; 1.4633x over previous
#include <cuda_runtime.h>
#include <cuda_bf16.h>
#include <mma.h>
#include <math.h>
#include <stdint.h>

using namespace nvcuda;

#define BB 4
#define CC 256
#define HW 4096
#define CK 2304
#define CPG 8
#define NPIX 16384
#define LDS 40
#define STAGE_ELEMS 15360   /* (256 + 128) rows * 40 */

// ---------------- scratch (device globals; no allocations) ----------------
__device__ __align__(128) float g_h  [(size_t)BB*CC*HW];
__device__ __align__(128) float g_f  [(size_t)BB*CC*HW];
__device__ __align__(128) float g_off[(size_t)BB*18*HW];
__device__ __align__(128) float g_h2 [(size_t)BB*CC*HW];
__device__ __align__(128) __nv_bfloat16 g_colh[(size_t)NPIX*CK];
__device__ __align__(128) __nv_bfloat16 g_coll[(size_t)NPIX*CK];
__device__ __align__(128) __nv_bfloat16 g_wh[(size_t)CC*CK];
__device__ __align__(128) __nv_bfloat16 g_wl[(size_t)CC*CK];

// ---------------- GroupNorm + ReLU (in: x or g_h2; out: g_h) ----------------
__global__ void gn_relu_kernel(const float* __restrict__ inp,
                               const float* __restrict__ gamma,
                               const float* __restrict__ beta) {
    const float* in = inp ? inp : (const float*)g_h2;
    int b = blockIdx.x >> 5, g = blockIdx.x & 31;
    size_t base = ((size_t)b*CC + g*CPG) * HW;
    const float4* p4 = (const float4*)(in + base);
    const int N4 = CPG*HW/4;
    float s = 0.f, s2 = 0.f;
    for (int i = threadIdx.x; i < N4; i += 256) {
        float4 v = p4[i];
        s  += v.x + v.y + v.z + v.w;
        s2 += v.x*v.x + v.y*v.y + v.z*v.z + v.w*v.w;
    }
    #pragma unroll
    for (int o = 16; o; o >>= 1) {
        s  += __shfl_xor_sync(0xffffffffu, s,  o);
        s2 += __shfl_xor_sync(0xffffffffu, s2, o);
    }
    __shared__ float sh[16];
    __shared__ float stats[2];
    int wid = threadIdx.x >> 5, lane = threadIdx.x & 31;
    if (lane == 0) { sh[wid] = s; sh[8 + wid] = s2; }
    __syncthreads();
    if (threadIdx.x == 0) {
        float ts = 0.f, ts2 = 0.f;
        #pragma unroll
        for (int i = 0; i < 8; i++) { ts += sh[i]; ts2 += sh[8+i]; }
        const float invN = 1.f / (float)(CPG*HW);
        float mean = ts * invN;
        float var  = ts2 * invN - mean*mean;
        stats[0] = mean;
        stats[1] = rsqrtf(var + 1e-5f);
    }
    __syncthreads();
    float mean = stats[0], inv = stats[1];
    float4* o4 = (float4*)(g_h + base);
    for (int i = threadIdx.x; i < N4; i += 256) {
        int c = g*CPG + (i >> 10);
        float ga = gamma[c] * inv;
        float be = beta[c] - mean * ga;
        float4 v = p4[i];
        v.x = fmaxf(fmaf(v.x, ga, be), 0.f);
        v.y = fmaxf(fmaf(v.y, ga, be), 0.f);
        v.z = fmaxf(fmaf(v.z, ga, be), 0.f);
        v.w = fmaxf(fmaf(v.w, ga, be), 0.f);
        o4[i] = v;
    }
}

// ---------------- Depthwise 7x7 SAME (g_h -> g_f) ----------------
__global__ void dw_conv_kernel(const float* __restrict__ wts) {
    int bc = blockIdx.x;
    int c = bc & (CC - 1);
    const float* p = g_h + (size_t)bc * HW;
    __shared__ float tile[70*70];
    __shared__ float wk[49];
    if (threadIdx.x < 49) wk[threadIdx.x] = wts[c*49 + threadIdx.x];
    for (int i = threadIdx.x; i < 70*70; i += 256) {
        int ty = i / 70 - 3, tx = i % 70 - 3;
        tile[i] = (ty >= 0 && ty < 64 && tx >= 0 && tx < 64) ? p[ty*64 + tx] : 0.f;
    }
    __syncthreads();
    int xg = (threadIdx.x & 15) * 4;
    int yb = threadIdx.x >> 4;
    #pragma unroll
    for (int it = 0; it < 4; it++) {
        int oy = it*16 + yb;
        float a0 = 0.f, a1 = 0.f, a2 = 0.f, a3 = 0.f;
        #pragma unroll
        for (int dy = 0; dy < 7; dy++) {
            const float* r = &tile[(oy+dy)*70 + xg];
            #pragma unroll
            for (int dx = 0; dx < 7; dx++) {
                float wv = wk[dy*7 + dx];
                a0 = fmaf(r[dx+0], wv, a0);
                a1 = fmaf(r[dx+1], wv, a1);
                a2 = fmaf(r[dx+2], wv, a2);
                a3 = fmaf(r[dx+3], wv, a3);
            }
        }
        float4 o4 = make_float4(a0, a1, a2, a3);
        *(float4*)&g_f[(size_t)bc*HW + oy*64 + xg] = o4;
    }
}

// ---------------- Pointwise 1x1 + bias (g_f -> g_off) ----------------
__global__ void pw_kernel(const float* __restrict__ pw,
                          const float* __restrict__ pwb) {
    int b = blockIdx.x >> 4;
    int p = (blockIdx.x & 15) * 256 + threadIdx.x;
    __shared__ float wsh[18*256];
    for (int i = threadIdx.x; i < 18*256; i += 256) wsh[i] = pw[i];
    __syncthreads();
    float acc[18];
    #pragma unroll
    for (int o = 0; o < 18; o++) acc[o] = 0.f;
    const float* fb = g_f + (size_t)b*CC*HW + p;
    for (int c = 0; c < CC; c++) {
        float v = fb[(size_t)c*HW];
        #pragma unroll
        for (int o = 0; o < 18; o++) acc[o] = fmaf(v, wsh[o*256 + c], acc[o]);
    }
    #pragma unroll
    for (int o = 0; o < 18; o++)
        g_off[((size_t)b*18 + o)*HW + p] = acc[o] + pwb[o];
}

// ---------------- im2col bilinear -> bf16 hi/lo, layout [pixel][k*256+c] ----------------
__device__ __forceinline__ unsigned int pack_bf2(__nv_bfloat16 a, __nv_bfloat16 b) {
    return (unsigned int)__bfloat16_as_ushort(a) |
           ((unsigned int)__bfloat16_as_ushort(b) << 16);
}
__global__ void im2col_bf16_kernel() {
    int blk = blockIdx.x;
    int pc = blk & 15;
    int k  = (blk >> 4) % 9;
    int b  = blk / 144;
    int p  = pc*256 + threadIdx.x;
    int yi = p >> 6, xi = p & 63;

    float offy = g_off[((size_t)b*18 + 2*k    )*HW + p];
    float offx = g_off[((size_t)b*18 + 2*k + 1)*HW + p];
    float py = (float)yi + (float)(k/3 - 1) + offy;
    float px = (float)xi + (float)(k%3 - 1) + offx;
    float y0f = floorf(py), x0f = floorf(px);
    float wy1 = py - y0f, wx1 = px - x0f;
    float wy0 = 1.f - wy1, wx0 = 1.f - wx1;
    float y1f = y0f + 1.f, x1f = x0f + 1.f;
    bool vy0 = (y0f >= 0.f) && (y0f <= 63.f);
    bool vy1 = (y1f >= 0.f) && (y1f <= 63.f);
    bool vx0 = (x0f >= 0.f) && (x0f <= 63.f);
    bool vx1 = (x1f >= 0.f) && (x1f <= 63.f);
    float w00 = (vy0 && vx0) ? wy0*wx0 : 0.f;
    float w01 = (vy0 && vx1) ? wy0*wx1 : 0.f;
    float w10 = (vy1 && vx0) ? wy1*wx0 : 0.f;
    float w11 = (vy1 && vx1) ? wy1*wx1 : 0.f;
    int yc0 = min(max((int)y0f, 0), 63);
    int yc1 = min(max((int)y1f, 0), 63);
    int xc0 = min(max((int)x0f, 0), 63);
    int xc1 = min(max((int)x1f, 0), 63);
    int i00 = yc0*64 + xc0, i01 = yc0*64 + xc1;
    int i10 = yc1*64 + xc0, i11 = yc1*64 + xc1;

    const float* xb = g_h + (size_t)b*CC*HW;
    size_t rowbase = ((size_t)b*HW + p)*CK + k*256;
    __nv_bfloat16* hp = g_colh + rowbase;
    __nv_bfloat16* lp = g_coll + rowbase;

    for (int c = 0; c < 256; c += 4) {
        float v[4];
        #pragma unroll
        for (int u = 0; u < 4; u++) {
            const float* pl = xb + (size_t)(c+u)*HW;
            float t = w00*pl[i00];
            t = fmaf(w01, pl[i01], t);
            t = fmaf(w10, pl[i10], t);
            t = fmaf(w11, pl[i11], t);
            v[u] = t;
        }
        __nv_bfloat16 hh[4], ll[4];
        #pragma unroll
        for (int u = 0; u < 4; u++) {
            hh[u] = __float2bfloat16(v[u]);
            ll[u] = __float2bfloat16(v[u] - __bfloat162float(hh[u]));
        }
        uint2 hv = make_uint2(pack_bf2(hh[0], hh[1]), pack_bf2(hh[2], hh[3]));
        uint2 lv = make_uint2(pack_bf2(ll[0], ll[1]), pack_bf2(ll[2], ll[3]));
        *(uint2*)(hp + c) = hv;
        *(uint2*)(lp + c) = lv;
    }
}

// ---------------- weight repack: [O][c*9+k] fp32 -> [O][k*256+c] bf16 hi/lo ----------------
__global__ void repack_w_kernel(const float* __restrict__ w) {
    int idx = blockIdx.x*256 + threadIdx.x;
    int o = idx / CK;
    int rem = idx - o*CK;
    int c = rem / 9;
    int k = rem - c*9;
    float v = w[idx];
    __nv_bfloat16 h = __float2bfloat16(v);
    float lo = v - __bfloat162float(h);
    int dst = o*CK + k*256 + c;
    g_wh[dst] = h;
    g_wl[dst] = __float2bfloat16(lo);
}

// ---------------- WMMA split-bf16 GEMM ----------------
// C[o,p] = sum_ck W[o,ck]*col[p,ck];  BM=128, BN=64, BK=32, 256 threads (8 warps 4x2)
// smem stage (bf16, ld=40): rows 0-127 Ah, 128-255 Al, 256-319 Bh, 320-383 Bl
#define SMEM_GEMM (2 * STAGE_ELEMS * 2)   /* 61440 bytes */

__device__ __forceinline__ void g2r(const __nv_bfloat16* gAh, const __nv_bfloat16* gAl,
                                    const __nv_bfloat16* gBh, const __nv_bfloat16* gBl,
                                    int ko, int tid, uint4* r) {
    #pragma unroll
    for (int u = 0; u < 4; u++) {
        int i = tid + u*256;
        int row = i >> 2;
        int c8 = (i & 3) * 8;
        const __nv_bfloat16* src = (row < 128) ? (gAh + (size_t)row*CK)
                                               : (gAl + (size_t)(row-128)*CK);
        r[u] = *(const uint4*)(src + ko + c8);
    }
    #pragma unroll
    for (int u = 0; u < 2; u++) {
        int i = tid + u*256;
        int row = i >> 2;
        int c8 = (i & 3) * 8;
        const __nv_bfloat16* src = (row < 64) ? (gBh + (size_t)row*CK)
                                              : (gBl + (size_t)(row-64)*CK);
        r[4+u] = *(const uint4*)(src + ko + c8);
    }
}
__device__ __forceinline__ void r2s(__nv_bfloat16* sbase, int tid, const uint4* r) {
    #pragma unroll
    for (int u = 0; u < 4; u++) {
        int i = tid + u*256;
        int row = i >> 2;
        int c8 = (i & 3) * 8;
        *(uint4*)(sbase + row*LDS + c8) = r[u];
    }
    #pragma unroll
    for (int u = 0; u < 2; u++) {
        int i = tid + u*256;
        int row = i >> 2;
        int c8 = (i & 3) * 8;
        *(uint4*)(sbase + (256 + row)*LDS + c8) = r[4+u];
    }
}

__global__ void __launch_bounds__(256, 2) gemm_wmma_kernel(
        const float* __restrict__ bias,
        const float* __restrict__ res,     // null or x (residual)
        float* __restrict__ outp) {        // null -> write g_h2
    extern __shared__ __align__(16) char smem[];
    __nv_bfloat16* sA = (__nv_bfloat16*)smem;
    int tid = threadIdx.x;
    int warp = tid >> 5;
    int wm = warp & 3;      // 0..3 -> M rows
    int wn = warp >> 2;     // 0..1 -> N cols
    int bn = blockIdx.x * 64;
    int bm = blockIdx.y * 128;
    float* out = outp ? outp : (float*)g_h2;

    const __nv_bfloat16* gAh = g_wh + (size_t)bm * CK;
    const __nv_bfloat16* gAl = g_wl + (size_t)bm * CK;
    const __nv_bfloat16* gBh = g_colh + (size_t)bn * CK;
    const __nv_bfloat16* gBl = g_coll + (size_t)bn * CK;

    wmma::fragment<wmma::accumulator, 16, 16, 16, float> acc[2][2];
    #pragma unroll
    for (int i = 0; i < 2; i++)
        #pragma unroll
        for (int j = 0; j < 2; j++)
            wmma::fill_fragment(acc[i][j], 0.f);

    uint4 rg[6];
    g2r(gAh, gAl, gBh, gBl, 0, tid, rg);
    r2s(sA, tid, rg);
    __syncthreads();

    const int NK = CK / 32;    // 72
    for (int kt = 0; kt < NK; kt++) {
        int s = kt & 1;
        if (kt + 1 < NK) g2r(gAh, gAl, gBh, gBl, (kt+1)*32, tid, rg);

        __nv_bfloat16* sb = sA + s * STAGE_ELEMS;
        #pragma unroll
        for (int kk = 0; kk < 32; kk += 16) {
            wmma::fragment<wmma::matrix_a, 16, 16, 16, __nv_bfloat16, wmma::row_major> fah[2], fal[2];
            wmma::fragment<wmma::matrix_b, 16, 16, 16, __nv_bfloat16, wmma::col_major> fbh[2], fbl[2];
            #pragma unroll
            for (int i = 0; i < 2; i++) {
                wmma::load_matrix_sync(fah[i], sb + (wm*32 + i*16)*LDS + kk, LDS);
                wmma::load_matrix_sync(fal[i], sb + (128 + wm*32 + i*16)*LDS + kk, LDS);
            }
            #pragma unroll
            for (int j = 0; j < 2; j++) {
                wmma::load_matrix_sync(fbh[j], sb + (256 + wn*32 + j*16)*LDS + kk, LDS);
                wmma::load_matrix_sync(fbl[j], sb + (320 + wn*32 + j*16)*LDS + kk, LDS);
            }
            #pragma unroll
            for (int i = 0; i < 2; i++)
                #pragma unroll
                for (int j = 0; j < 2; j++) {
                    wmma::mma_sync(acc[i][j], fah[i], fbh[j], acc[i][j]);
                    wmma::mma_sync(acc[i][j], fah[i], fbl[j], acc[i][j]);
                    wmma::mma_sync(acc[i][j], fal[i], fbh[j], acc[i][j]);
                }
        }

        if (kt + 1 < NK) r2s(sA + (s^1) * STAGE_ELEMS, tid, rg);
        __syncthreads();
    }

    // epilogue: park accumulators in smem (reuse stage memory), then fused write
    float* sOut = (float*)smem;   // 128 x 64 floats = 32KB
    #pragma unroll
    for (int i = 0; i < 2; i++)
        #pragma unroll
        for (int j = 0; j < 2; j++)
            wmma::store_matrix_sync(sOut + (wm*32 + i*16)*64 + (wn*32 + j*16),
                                    acc[i][j], 64, wmma::mem_row_major);
    __syncthreads();

    int b = bn >> 12;
    int pin = bn & 4095;
    int r0 = tid >> 4;           // 0..15
    int c4 = (tid & 15) * 4;     // 0..60
    #pragma unroll
    for (int i = 0; i < 8; i++) {
        int row = r0 + i*16;
        int o = bm + row;
        float4 v = *(float4*)(sOut + row*64 + c4);
        float bs = bias[o];
        v.x += bs; v.y += bs; v.z += bs; v.w += bs;
        size_t off = ((size_t)(b*256 + o))*4096 + pin + c4;
        if (res) {
            float4 rr = *(const float4*)(res + off);
            v.x += rr.x; v.y += rr.y; v.z += rr.z; v.w += rr.w;
        }
        *(float4*)(out + off) = v;
    }
}

// ---------------- launch ----------------
extern "C" void kernel_launch(void* const* d_in, const int* in_sizes, int n_in,
                              void* d_out, int out_size) {
    const float* x    = (const float*)d_in[0];
    const float* gn1g = (const float*)d_in[1];
    const float* gn1b = (const float*)d_in[2];
    const float* dw1  = (const float*)d_in[3];
    const float* pw1  = (const float*)d_in[4];
    const float* pwb1 = (const float*)d_in[5];
    const float* w1   = (const float*)d_in[6];
    const float* b1   = (const float*)d_in[7];
    const float* gn2g = (const float*)d_in[8];
    const float* gn2b = (const float*)d_in[9];
    const float* dw2  = (const float*)d_in[10];
    const float* pw2  = (const float*)d_in[11];
    const float* pwb2 = (const float*)d_in[12];
    const float* w2   = (const float*)d_in[13];
    const float* b2   = (const float*)d_in[14];
    float* out = (float*)d_out;

    cudaFuncSetAttribute(gemm_wmma_kernel, cudaFuncAttributeMaxDynamicSharedMemorySize, SMEM_GEMM);

    // stage 1
    gn_relu_kernel<<<128, 256>>>(x, gn1g, gn1b);
    dw_conv_kernel<<<BB*CC, 256>>>(dw1);
    pw_kernel<<<64, 256>>>(pw1, pwb1);
    im2col_bf16_kernel<<<576, 256>>>();
    repack_w_kernel<<<CC*CK/256, 256>>>(w1);
    gemm_wmma_kernel<<<dim3(256, 2), 256, SMEM_GEMM>>>(b1, nullptr, nullptr);

    // stage 2
    gn_relu_kernel<<<128, 256>>>(nullptr, gn2g, gn2b);
    dw_conv_kernel<<<BB*CC, 256>>>(dw2);
    pw_kernel<<<64, 256>>>(pw2, pwb2);
    im2col_bf16_kernel<<<576, 256>>>();
    repack_w_kernel<<<CC*CK/256, 256>>>(w2);
    gemm_wmma_kernel<<<dim3(256, 2), 256, SMEM_GEMM>>>(b2, x, out);
}

// round 9
// speedup vs baseline: 1.5026x; 1.0269x over previous
#include <cuda_runtime.h>
#include <cuda_bf16.h>
#include <mma.h>
#include <cuda_pipeline.h>
#include <math.h>
#include <stdint.h>

using namespace nvcuda;

#define BB 4
#define CC 256
#define HW 4096
#define CK 2304
#define CPG 8
#define NPIX 16384
#define LDS 40
#define SROWS 512                 /* 128 Ah + 128 Al + 128 Bh + 128 Bl */
#define STG (SROWS*LDS)           /* 20480 bf16 elems per stage */
#define SMEM_GEMM (2*STG*2)       /* 81920 bytes */

// ---------------- scratch (device globals; no allocations) ----------------
__device__ __align__(128) float g_h  [(size_t)BB*CC*HW];
__device__ __align__(128) float g_f  [(size_t)BB*CC*HW];
__device__ __align__(128) float g_off[(size_t)BB*18*HW];
__device__ __align__(128) float g_h2 [(size_t)BB*CC*HW];
__device__ __align__(128) __nv_bfloat16 g_colh[(size_t)NPIX*CK];
__device__ __align__(128) __nv_bfloat16 g_coll[(size_t)NPIX*CK];
__device__ __align__(128) __nv_bfloat16 g_wh[(size_t)CC*CK];
__device__ __align__(128) __nv_bfloat16 g_wl[(size_t)CC*CK];

// ---------------- GroupNorm + ReLU (in: x or g_h2; out: g_h) ----------------
__global__ void gn_relu_kernel(const float* __restrict__ inp,
                               const float* __restrict__ gamma,
                               const float* __restrict__ beta) {
    const float* in = inp ? inp : (const float*)g_h2;
    int b = blockIdx.x >> 5, g = blockIdx.x & 31;
    size_t base = ((size_t)b*CC + g*CPG) * HW;
    const float4* p4 = (const float4*)(in + base);
    const int N4 = CPG*HW/4;
    float s = 0.f, s2 = 0.f;
    for (int i = threadIdx.x; i < N4; i += 256) {
        float4 v = p4[i];
        s  += v.x + v.y + v.z + v.w;
        s2 += v.x*v.x + v.y*v.y + v.z*v.z + v.w*v.w;
    }
    #pragma unroll
    for (int o = 16; o; o >>= 1) {
        s  += __shfl_xor_sync(0xffffffffu, s,  o);
        s2 += __shfl_xor_sync(0xffffffffu, s2, o);
    }
    __shared__ float sh[16];
    __shared__ float stats[2];
    int wid = threadIdx.x >> 5, lane = threadIdx.x & 31;
    if (lane == 0) { sh[wid] = s; sh[8 + wid] = s2; }
    __syncthreads();
    if (threadIdx.x == 0) {
        float ts = 0.f, ts2 = 0.f;
        #pragma unroll
        for (int i = 0; i < 8; i++) { ts += sh[i]; ts2 += sh[8+i]; }
        const float invN = 1.f / (float)(CPG*HW);
        float mean = ts * invN;
        float var  = ts2 * invN - mean*mean;
        stats[0] = mean;
        stats[1] = rsqrtf(var + 1e-5f);
    }
    __syncthreads();
    float mean = stats[0], inv = stats[1];
    float4* o4 = (float4*)(g_h + base);
    for (int i = threadIdx.x; i < N4; i += 256) {
        int c = g*CPG + (i >> 10);
        float ga = gamma[c] * inv;
        float be = beta[c] - mean * ga;
        float4 v = p4[i];
        v.x = fmaxf(fmaf(v.x, ga, be), 0.f);
        v.y = fmaxf(fmaf(v.y, ga, be), 0.f);
        v.z = fmaxf(fmaf(v.z, ga, be), 0.f);
        v.w = fmaxf(fmaf(v.w, ga, be), 0.f);
        o4[i] = v;
    }
}

// ---------------- Depthwise 7x7 SAME (g_h -> g_f) ----------------
__global__ void dw_conv_kernel(const float* __restrict__ wts) {
    int bc = blockIdx.x;
    int c = bc & (CC - 1);
    const float* p = g_h + (size_t)bc * HW;
    __shared__ float tile[70*70];
    __shared__ float wk[49];
    if (threadIdx.x < 49) wk[threadIdx.x] = wts[c*49 + threadIdx.x];
    for (int i = threadIdx.x; i < 70*70; i += 256) {
        int ty = i / 70 - 3, tx = i % 70 - 3;
        tile[i] = (ty >= 0 && ty < 64 && tx >= 0 && tx < 64) ? p[ty*64 + tx] : 0.f;
    }
    __syncthreads();
    int xg = (threadIdx.x & 15) * 4;
    int yb = threadIdx.x >> 4;
    #pragma unroll
    for (int it = 0; it < 4; it++) {
        int oy = it*16 + yb;
        float a0 = 0.f, a1 = 0.f, a2 = 0.f, a3 = 0.f;
        #pragma unroll
        for (int dy = 0; dy < 7; dy++) {
            const float* r = &tile[(oy+dy)*70 + xg];
            #pragma unroll
            for (int dx = 0; dx < 7; dx++) {
                float wv = wk[dy*7 + dx];
                a0 = fmaf(r[dx+0], wv, a0);
                a1 = fmaf(r[dx+1], wv, a1);
                a2 = fmaf(r[dx+2], wv, a2);
                a3 = fmaf(r[dx+3], wv, a3);
            }
        }
        float4 o4 = make_float4(a0, a1, a2, a3);
        *(float4*)&g_f[(size_t)bc*HW + oy*64 + xg] = o4;
    }
}

// ---------------- Pointwise 1x1 + bias (g_f -> g_off) ----------------
__global__ void pw_kernel(const float* __restrict__ pw,
                          const float* __restrict__ pwb) {
    int b = blockIdx.x >> 4;
    int p = (blockIdx.x & 15) * 256 + threadIdx.x;
    __shared__ float wsh[18*256];
    for (int i = threadIdx.x; i < 18*256; i += 256) wsh[i] = pw[i];
    __syncthreads();
    float acc[18];
    #pragma unroll
    for (int o = 0; o < 18; o++) acc[o] = 0.f;
    const float* fb = g_f + (size_t)b*CC*HW + p;
    for (int c = 0; c < CC; c++) {
        float v = fb[(size_t)c*HW];
        #pragma unroll
        for (int o = 0; o < 18; o++) acc[o] = fmaf(v, wsh[o*256 + c], acc[o]);
    }
    #pragma unroll
    for (int o = 0; o < 18; o++)
        g_off[((size_t)b*18 + o)*HW + p] = acc[o] + pwb[o];
}

// ---------------- im2col bilinear -> bf16 hi/lo, layout [pixel][k*256+c] ----------------
// grid = 1152: pc(16) x ch(2) x k(9) x b(4); each block does 128 channels
__device__ __forceinline__ unsigned int pack_bf2(__nv_bfloat16 a, __nv_bfloat16 b) {
    return (unsigned int)__bfloat16_as_ushort(a) |
           ((unsigned int)__bfloat16_as_ushort(b) << 16);
}
__global__ void im2col_bf16_kernel() {
    int blk = blockIdx.x;
    int pc = blk & 15;
    int t2 = blk >> 4;
    int ch = t2 & 1;
    t2 >>= 1;
    int k = t2 % 9;
    int b = t2 / 9;
    int p  = pc*256 + threadIdx.x;
    int yi = p >> 6, xi = p & 63;

    float offy = g_off[((size_t)b*18 + 2*k    )*HW + p];
    float offx = g_off[((size_t)b*18 + 2*k + 1)*HW + p];
    float py = (float)yi + (float)(k/3 - 1) + offy;
    float px = (float)xi + (float)(k%3 - 1) + offx;
    float y0f = floorf(py), x0f = floorf(px);
    float wy1 = py - y0f, wx1 = px - x0f;
    float wy0 = 1.f - wy1, wx0 = 1.f - wx1;
    float y1f = y0f + 1.f, x1f = x0f + 1.f;
    bool vy0 = (y0f >= 0.f) && (y0f <= 63.f);
    bool vy1 = (y1f >= 0.f) && (y1f <= 63.f);
    bool vx0 = (x0f >= 0.f) && (x0f <= 63.f);
    bool vx1 = (x1f >= 0.f) && (x1f <= 63.f);
    float w00 = (vy0 && vx0) ? wy0*wx0 : 0.f;
    float w01 = (vy0 && vx1) ? wy0*wx1 : 0.f;
    float w10 = (vy1 && vx0) ? wy1*wx0 : 0.f;
    float w11 = (vy1 && vx1) ? wy1*wx1 : 0.f;
    int yc0 = min(max((int)y0f, 0), 63);
    int yc1 = min(max((int)y1f, 0), 63);
    int xc0 = min(max((int)x0f, 0), 63);
    int xc1 = min(max((int)x1f, 0), 63);
    int i00 = yc0*64 + xc0, i01 = yc0*64 + xc1;
    int i10 = yc1*64 + xc0, i11 = yc1*64 + xc1;

    const float* xb = g_h + (size_t)b*CC*HW;
    size_t rowbase = ((size_t)b*HW + p)*CK + k*256;
    __nv_bfloat16* hp = g_colh + rowbase;
    __nv_bfloat16* lp = g_coll + rowbase;

    int c0 = ch*128;
    for (int c = c0; c < c0 + 128; c += 4) {
        float v[4];
        #pragma unroll
        for (int u = 0; u < 4; u++) {
            const float* pl = xb + (size_t)(c+u)*HW;
            float t = w00*pl[i00];
            t = fmaf(w01, pl[i01], t);
            t = fmaf(w10, pl[i10], t);
            t = fmaf(w11, pl[i11], t);
            v[u] = t;
        }
        __nv_bfloat16 hh[4], ll[4];
        #pragma unroll
        for (int u = 0; u < 4; u++) {
            hh[u] = __float2bfloat16(v[u]);
            ll[u] = __float2bfloat16(v[u] - __bfloat162float(hh[u]));
        }
        uint2 hv = make_uint2(pack_bf2(hh[0], hh[1]), pack_bf2(hh[2], hh[3]));
        uint2 lv = make_uint2(pack_bf2(ll[0], ll[1]), pack_bf2(ll[2], ll[3]));
        *(uint2*)(hp + c) = hv;
        *(uint2*)(lp + c) = lv;
    }
}

// ---------------- weight repack: [O][c*9+k] fp32 -> [O][k*256+c] bf16 hi/lo ----------------
__global__ void repack_w_kernel(const float* __restrict__ w) {
    int idx = blockIdx.x*256 + threadIdx.x;
    int o = idx / CK;
    int rem = idx - o*CK;
    int c = rem / 9;
    int k = rem - c*9;
    float v = w[idx];
    __nv_bfloat16 h = __float2bfloat16(v);
    float lo = v - __bfloat162float(h);
    int dst = o*CK + k*256 + c;
    g_wh[dst] = h;
    g_wl[dst] = __float2bfloat16(lo);
}

// ---------------- WMMA split-bf16 GEMM ----------------
// C[o,p] = sum_ck W[o,ck]*col[p,ck]; BM=128, BN=128, BK=32, 512 threads (16 warps 4x4)
// smem stage (bf16, ld=40): rows 0-127 Ah, 128-255 Al, 256-383 Bh, 384-511 Bl
__global__ void __launch_bounds__(512) gemm_wmma_kernel(
        const float* __restrict__ bias,
        const float* __restrict__ res,     // null or x (residual)
        float* __restrict__ outp) {        // null -> write g_h2
    extern __shared__ __align__(16) char smem[];
    __nv_bfloat16* sA = (__nv_bfloat16*)smem;
    int tid = threadIdx.x;
    int warp = tid >> 5;
    int wm = warp & 3;      // 0..3 -> M (32-row tiles)
    int wn = warp >> 2;     // 0..3 -> N (32-col tiles)
    int bn = blockIdx.x * 128;
    int bm = blockIdx.y * 128;
    float* out = outp ? outp : (float*)g_h2;

    const __nv_bfloat16* gAh = g_wh + (size_t)bm * CK;
    const __nv_bfloat16* gAl = g_wl + (size_t)bm * CK;
    const __nv_bfloat16* gBh = g_colh + (size_t)bn * CK;
    const __nv_bfloat16* gBl = g_coll + (size_t)bn * CK;

    wmma::fragment<wmma::accumulator, 16, 16, 16, float> acc[2][2];
    #pragma unroll
    for (int i = 0; i < 2; i++)
        #pragma unroll
        for (int j = 0; j < 2; j++)
            wmma::fill_fragment(acc[i][j], 0.f);

    // async stage loader: 2048 16B-chunks per stage, 4 per thread
    auto load_stage = [&](int buf, int kt) {
        __nv_bfloat16* sb = sA + buf * STG;
        int ko = kt * 32;
        #pragma unroll
        for (int u = 0; u < 4; u++) {
            int i = tid + u*512;
            int row = i >> 2;
            int c8 = (i & 3) * 8;
            const __nv_bfloat16* src;
            if (row < 128)      src = gAh + (size_t)row*CK;
            else if (row < 256) src = gAl + (size_t)(row-128)*CK;
            else if (row < 384) src = gBh + (size_t)(row-256)*CK;
            else                src = gBl + (size_t)(row-384)*CK;
            __pipeline_memcpy_async(sb + row*LDS + c8, src + ko + c8, 16);
        }
        __pipeline_commit();
    };

    load_stage(0, 0);

    const int NK = CK / 32;    // 72
    for (int kt = 0; kt < NK; kt++) {
        int s = kt & 1;
        if (kt + 1 < NK) {
            load_stage(s ^ 1, kt + 1);
            __pipeline_wait_prior(1);
        } else {
            __pipeline_wait_prior(0);
        }
        __syncthreads();

        __nv_bfloat16* sb = sA + s * STG;
        #pragma unroll
        for (int kk = 0; kk < 32; kk += 16) {
            wmma::fragment<wmma::matrix_a, 16, 16, 16, __nv_bfloat16, wmma::row_major> fah[2], fal[2];
            #pragma unroll
            for (int i = 0; i < 2; i++) {
                wmma::load_matrix_sync(fah[i], sb + (wm*32 + i*16)*LDS + kk, LDS);
                wmma::load_matrix_sync(fal[i], sb + (128 + wm*32 + i*16)*LDS + kk, LDS);
            }
            #pragma unroll
            for (int j = 0; j < 2; j++) {
                wmma::fragment<wmma::matrix_b, 16, 16, 16, __nv_bfloat16, wmma::col_major> fbh, fbl;
                wmma::load_matrix_sync(fbh, sb + (256 + wn*32 + j*16)*LDS + kk, LDS);
                wmma::load_matrix_sync(fbl, sb + (384 + wn*32 + j*16)*LDS + kk, LDS);
                #pragma unroll
                for (int i = 0; i < 2; i++) {
                    wmma::mma_sync(acc[i][j], fah[i], fbh, acc[i][j]);
                    wmma::mma_sync(acc[i][j], fah[i], fbl, acc[i][j]);
                    wmma::mma_sync(acc[i][j], fal[i], fbh, acc[i][j]);
                }
            }
        }
        __syncthreads();
    }

    // epilogue: park accumulators in smem, then fused bias/residual write
    float* sOut = (float*)smem;   // 128 x 128 floats = 64KB (fits in 80KB)
    #pragma unroll
    for (int i = 0; i < 2; i++)
        #pragma unroll
        for (int j = 0; j < 2; j++)
            wmma::store_matrix_sync(sOut + (wm*32 + i*16)*128 + (wn*32 + j*16),
                                    acc[i][j], 128, wmma::mem_row_major);
    __syncthreads();

    int b = bn >> 12;
    int pin = bn & 4095;
    int r0 = tid >> 5;            // 0..15
    int c4 = (tid & 31) * 4;      // 0..124
    #pragma unroll
    for (int i = 0; i < 8; i++) {
        int row = r0 + i*16;
        int o = bm + row;
        float4 v = *(float4*)(sOut + row*128 + c4);
        float bs = bias[o];
        v.x += bs; v.y += bs; v.z += bs; v.w += bs;
        size_t off = ((size_t)(b*256 + o))*4096 + pin + c4;
        if (res) {
            float4 rr = *(const float4*)(res + off);
            v.x += rr.x; v.y += rr.y; v.z += rr.z; v.w += rr.w;
        }
        *(float4*)(out + off) = v;
    }
}

// ---------------- launch ----------------
extern "C" void kernel_launch(void* const* d_in, const int* in_sizes, int n_in,
                              void* d_out, int out_size) {
    const float* x    = (const float*)d_in[0];
    const float* gn1g = (const float*)d_in[1];
    const float* gn1b = (const float*)d_in[2];
    const float* dw1  = (const float*)d_in[3];
    const float* pw1  = (const float*)d_in[4];
    const float* pwb1 = (const float*)d_in[5];
    const float* w1   = (const float*)d_in[6];
    const float* b1   = (const float*)d_in[7];
    const float* gn2g = (const float*)d_in[8];
    const float* gn2b = (const float*)d_in[9];
    const float* dw2  = (const float*)d_in[10];
    const float* pw2  = (const float*)d_in[11];
    const float* pwb2 = (const float*)d_in[12];
    const float* w2   = (const float*)d_in[13];
    const float* b2   = (const float*)d_in[14];
    float* out = (float*)d_out;

    cudaFuncSetAttribute(gemm_wmma_kernel, cudaFuncAttributeMaxDynamicSharedMemorySize, SMEM_GEMM);

    // stage 1
    gn_relu_kernel<<<128, 256>>>(x, gn1g, gn1b);
    dw_conv_kernel<<<BB*CC, 256>>>(dw1);
    pw_kernel<<<64, 256>>>(pw1, pwb1);
    im2col_bf16_kernel<<<1152, 256>>>();
    repack_w_kernel<<<CC*CK/256, 256>>>(w1);
    gemm_wmma_kernel<<<dim3(128, 2), 512, SMEM_GEMM>>>(b1, nullptr, nullptr);

    // stage 2
    gn_relu_kernel<<<128, 256>>>(nullptr, gn2g, gn2b);
    dw_conv_kernel<<<BB*CC, 256>>>(dw2);
    pw_kernel<<<64, 256>>>(pw2, pwb2);
    im2col_bf16_kernel<<<1152, 256>>>();
    repack_w_kernel<<<CC*CK/256, 256>>>(w2);
    gemm_wmma_kernel<<<dim3(128, 2), 512, SMEM_GEMM>>>(b2, x, out);
}

// round 10
// speedup vs baseline: 2.1473x; 1.4291x over previous
#include <cuda_runtime.h>
#include <cuda_bf16.h>
#include <mma.h>
#include <cuda_pipeline.h>
#include <math.h>
#include <stdint.h>

using namespace nvcuda;

#define BB 4
#define CC 256
#define HW 4096
#define CK 2304
#define CPG 8
#define NPIX 16384
#define LDA 40
#define LDB 136
#define A_ELEMS (512*LDA)              /* 20480 */
#define STGE (A_ELEMS + 64*LDB)        /* 29184 elems per stage */
#define SMEM_GEMM 131072               /* epilogue 256x128 fp32; >= 2 stages (116736B) */

// ---------------- scratch (device globals; no allocations) ----------------
__device__ __align__(128) float g_h  [(size_t)BB*CC*HW];
__device__ __align__(128) float g_f  [(size_t)BB*CC*HW];
__device__ __align__(128) float g_off[(size_t)BB*18*HW];
__device__ __align__(128) float g_h2 [(size_t)BB*CC*HW];
__device__ __align__(128) __nv_bfloat16 g_colh[(size_t)CK*NPIX];   // [K][pixels]
__device__ __align__(128) __nv_bfloat16 g_coll[(size_t)CK*NPIX];
__device__ __align__(128) __nv_bfloat16 g_wh[(size_t)CC*CK];
__device__ __align__(128) __nv_bfloat16 g_wl[(size_t)CC*CK];

// ---------------- GroupNorm + ReLU (in: x or g_h2; out: g_h) ----------------
__global__ void gn_relu_kernel(const float* __restrict__ inp,
                               const float* __restrict__ gamma,
                               const float* __restrict__ beta) {
    const float* in = inp ? inp : (const float*)g_h2;
    int b = blockIdx.x >> 5, g = blockIdx.x & 31;
    size_t base = ((size_t)b*CC + g*CPG) * HW;
    const float4* p4 = (const float4*)(in + base);
    const int N4 = CPG*HW/4;
    float s = 0.f, s2 = 0.f;
    for (int i = threadIdx.x; i < N4; i += 256) {
        float4 v = p4[i];
        s  += v.x + v.y + v.z + v.w;
        s2 += v.x*v.x + v.y*v.y + v.z*v.z + v.w*v.w;
    }
    #pragma unroll
    for (int o = 16; o; o >>= 1) {
        s  += __shfl_xor_sync(0xffffffffu, s,  o);
        s2 += __shfl_xor_sync(0xffffffffu, s2, o);
    }
    __shared__ float sh[16];
    __shared__ float stats[2];
    int wid = threadIdx.x >> 5, lane = threadIdx.x & 31;
    if (lane == 0) { sh[wid] = s; sh[8 + wid] = s2; }
    __syncthreads();
    if (threadIdx.x == 0) {
        float ts = 0.f, ts2 = 0.f;
        #pragma unroll
        for (int i = 0; i < 8; i++) { ts += sh[i]; ts2 += sh[8+i]; }
        const float invN = 1.f / (float)(CPG*HW);
        float mean = ts * invN;
        float var  = ts2 * invN - mean*mean;
        stats[0] = mean;
        stats[1] = rsqrtf(var + 1e-5f);
    }
    __syncthreads();
    float mean = stats[0], inv = stats[1];
    float4* o4 = (float4*)(g_h + base);
    for (int i = threadIdx.x; i < N4; i += 256) {
        int c = g*CPG + (i >> 10);
        float ga = gamma[c] * inv;
        float be = beta[c] - mean * ga;
        float4 v = p4[i];
        v.x = fmaxf(fmaf(v.x, ga, be), 0.f);
        v.y = fmaxf(fmaf(v.y, ga, be), 0.f);
        v.z = fmaxf(fmaf(v.z, ga, be), 0.f);
        v.w = fmaxf(fmaf(v.w, ga, be), 0.f);
        o4[i] = v;
    }
}

// ---------------- Depthwise 7x7 SAME (g_h -> g_f) ----------------
__global__ void dw_conv_kernel(const float* __restrict__ wts) {
    int bc = blockIdx.x;
    int c = bc & (CC - 1);
    const float* p = g_h + (size_t)bc * HW;
    __shared__ float tile[70*70];
    __shared__ float wk[49];
    if (threadIdx.x < 49) wk[threadIdx.x] = wts[c*49 + threadIdx.x];
    for (int i = threadIdx.x; i < 70*70; i += 256) {
        int ty = i / 70 - 3, tx = i % 70 - 3;
        tile[i] = (ty >= 0 && ty < 64 && tx >= 0 && tx < 64) ? p[ty*64 + tx] : 0.f;
    }
    __syncthreads();
    int xg = (threadIdx.x & 15) * 4;
    int yb = threadIdx.x >> 4;
    #pragma unroll
    for (int it = 0; it < 4; it++) {
        int oy = it*16 + yb;
        float a0 = 0.f, a1 = 0.f, a2 = 0.f, a3 = 0.f;
        #pragma unroll
        for (int dy = 0; dy < 7; dy++) {
            const float* r = &tile[(oy+dy)*70 + xg];
            #pragma unroll
            for (int dx = 0; dx < 7; dx++) {
                float wv = wk[dy*7 + dx];
                a0 = fmaf(r[dx+0], wv, a0);
                a1 = fmaf(r[dx+1], wv, a1);
                a2 = fmaf(r[dx+2], wv, a2);
                a3 = fmaf(r[dx+3], wv, a3);
            }
        }
        float4 o4 = make_float4(a0, a1, a2, a3);
        *(float4*)&g_f[(size_t)bc*HW + oy*64 + xg] = o4;
    }
}

// ---------------- Pointwise 1x1 + bias (g_f -> g_off) ----------------
__global__ void pw_kernel(const float* __restrict__ pw,
                          const float* __restrict__ pwb) {
    int b = blockIdx.x >> 4;
    int p = (blockIdx.x & 15) * 256 + threadIdx.x;
    __shared__ float wsh[18*256];
    for (int i = threadIdx.x; i < 18*256; i += 256) wsh[i] = pw[i];
    __syncthreads();
    float acc[18];
    #pragma unroll
    for (int o = 0; o < 18; o++) acc[o] = 0.f;
    const float* fb = g_f + (size_t)b*CC*HW + p;
    for (int c = 0; c < CC; c++) {
        float v = fb[(size_t)c*HW];
        #pragma unroll
        for (int o = 0; o < 18; o++) acc[o] = fmaf(v, wsh[o*256 + c], acc[o]);
    }
    #pragma unroll
    for (int o = 0; o < 18; o++)
        g_off[((size_t)b*18 + o)*HW + p] = acc[o] + pwb[o];
}

// ---------------- im2col bilinear -> bf16 hi/lo, layout [k*256+c][b*HW+p] ----------------
// grid = 576: pc(8) x ch(2) x k(9) x b(4); 256 threads; each thread = 2 adjacent pixels, 128 ch
__device__ __forceinline__ unsigned int pack_bf2(__nv_bfloat16 a, __nv_bfloat16 b) {
    return (unsigned int)__bfloat16_as_ushort(a) |
           ((unsigned int)__bfloat16_as_ushort(b) << 16);
}
__global__ void im2col_bf16_kernel() {
    int blk = blockIdx.x;
    int pc = blk & 7;
    int t2 = blk >> 3;
    int ch = t2 & 1;
    t2 >>= 1;
    int k = t2 % 9;
    int b = t2 / 9;
    int p0 = pc*512 + threadIdx.x*2;

    float ky = (float)(k/3 - 1), kx = (float)(k%3 - 1);
    int idx[2][4];
    float wgt[2][4];
    #pragma unroll
    for (int e = 0; e < 2; e++) {
        int p = p0 + e;
        int yi = p >> 6, xi = p & 63;
        float offy = g_off[((size_t)b*18 + 2*k    )*HW + p];
        float offx = g_off[((size_t)b*18 + 2*k + 1)*HW + p];
        float py = (float)yi + ky + offy;
        float px = (float)xi + kx + offx;
        float y0f = floorf(py), x0f = floorf(px);
        float wy1 = py - y0f, wx1 = px - x0f;
        float wy0 = 1.f - wy1, wx0 = 1.f - wx1;
        float y1f = y0f + 1.f, x1f = x0f + 1.f;
        bool vy0 = (y0f >= 0.f) && (y0f <= 63.f);
        bool vy1 = (y1f >= 0.f) && (y1f <= 63.f);
        bool vx0 = (x0f >= 0.f) && (x0f <= 63.f);
        bool vx1 = (x1f >= 0.f) && (x1f <= 63.f);
        wgt[e][0] = (vy0 && vx0) ? wy0*wx0 : 0.f;
        wgt[e][1] = (vy0 && vx1) ? wy0*wx1 : 0.f;
        wgt[e][2] = (vy1 && vx0) ? wy1*wx0 : 0.f;
        wgt[e][3] = (vy1 && vx1) ? wy1*wx1 : 0.f;
        int yc0 = min(max((int)y0f, 0), 63);
        int yc1 = min(max((int)y1f, 0), 63);
        int xc0 = min(max((int)x0f, 0), 63);
        int xc1 = min(max((int)x1f, 0), 63);
        idx[e][0] = yc0*64 + xc0;
        idx[e][1] = yc0*64 + xc1;
        idx[e][2] = yc1*64 + xc0;
        idx[e][3] = yc1*64 + xc1;
    }

    const float* xb = g_h + (size_t)b*CC*HW;
    size_t gcol = (size_t)b*HW + p0;   // pixel coordinate (even -> 4B aligned)
    int c0 = ch*128;
    #pragma unroll 4
    for (int c = c0; c < c0 + 128; c++) {
        const float* pl = xb + (size_t)c*HW;
        float v[2];
        #pragma unroll
        for (int e = 0; e < 2; e++) {
            float t = wgt[e][0]*pl[idx[e][0]];
            t = fmaf(wgt[e][1], pl[idx[e][1]], t);
            t = fmaf(wgt[e][2], pl[idx[e][2]], t);
            t = fmaf(wgt[e][3], pl[idx[e][3]], t);
            v[e] = t;
        }
        __nv_bfloat16 h0 = __float2bfloat16(v[0]);
        __nv_bfloat16 h1 = __float2bfloat16(v[1]);
        __nv_bfloat16 l0 = __float2bfloat16(v[0] - __bfloat162float(h0));
        __nv_bfloat16 l1 = __float2bfloat16(v[1] - __bfloat162float(h1));
        size_t row = (size_t)(k*256 + c) * NPIX + gcol;
        *(unsigned int*)(g_colh + row) = pack_bf2(h0, h1);
        *(unsigned int*)(g_coll + row) = pack_bf2(l0, l1);
    }
}

// ---------------- weight repack: [O][c*9+k] fp32 -> [O][k*256+c] bf16 hi/lo ----------------
__global__ void repack_w_kernel(const float* __restrict__ w) {
    int idx = blockIdx.x*256 + threadIdx.x;
    int o = idx / CK;
    int rem = idx - o*CK;
    int c = rem / 9;
    int k = rem - c*9;
    float v = w[idx];
    __nv_bfloat16 h = __float2bfloat16(v);
    float lo = v - __bfloat162float(h);
    int dst = o*CK + k*256 + c;
    g_wh[dst] = h;
    g_wl[dst] = __float2bfloat16(lo);
}

// ---------------- WMMA split-bf16 GEMM ----------------
// C[o,p] = sum_ck W[o,ck]*col[ck,p]; BM=256 (all M), BN=128, BK=32
// 512 threads = 16 warps (4x4); warp tile 64x32 -> acc[4][2]
// smem stage (bf16): rows 0-255 Ah, 256-511 Al (ld=40); then 64 B-rows (32 Bh + 32 Bl, ld=136)
__global__ void __launch_bounds__(512, 1) gemm_wmma_kernel(
        const float* __restrict__ bias,
        const float* __restrict__ res,     // null or x (residual)
        float* __restrict__ outp) {        // null -> write g_h2
    extern __shared__ __align__(16) char smem[];
    __nv_bfloat16* sA = (__nv_bfloat16*)smem;
    int tid = threadIdx.x;
    int warp = tid >> 5;
    int wm = warp & 3;      // 0..3 -> 64-row tiles
    int wn = warp >> 2;     // 0..3 -> 32-col tiles
    int bn = blockIdx.x * 128;
    float* out = outp ? outp : (float*)g_h2;

    wmma::fragment<wmma::accumulator, 16, 16, 16, float> acc[4][2];
    #pragma unroll
    for (int i = 0; i < 4; i++)
        #pragma unroll
        for (int j = 0; j < 2; j++)
            wmma::fill_fragment(acc[i][j], 0.f);

    // stage loader: 3072 16B-chunks (2048 A + 1024 B), 6 per thread
    auto load_stage = [&](int buf, int kt) {
        __nv_bfloat16* sb = sA + buf * STGE;
        int ko = kt * 32;
        #pragma unroll
        for (int u = 0; u < 6; u++) {
            int i = tid + u*512;
            const __nv_bfloat16* src;
            __nv_bfloat16* dst;
            if (i < 2048) {
                int row = i >> 2;
                int c8 = (i & 3) * 8;
                src = (row < 256 ? g_wh + (size_t)row*CK
                                 : g_wl + (size_t)(row-256)*CK) + ko + c8;
                dst = sb + row*LDA + c8;
            } else {
                int j = i - 2048;
                int row = j >> 4;            // 0..63
                int e8 = (j & 15) * 8;       // 0..120
                int ck = ko + (row & 31);
                src = (row < 32 ? g_colh : g_coll) + (size_t)ck*NPIX + bn + e8;
                dst = sb + A_ELEMS + row*LDB + e8;
            }
            __pipeline_memcpy_async(dst, src, 16);
        }
        __pipeline_commit();
    };

    load_stage(0, 0);

    const int NK = CK / 32;    // 72
    for (int kt = 0; kt < NK; kt++) {
        int s = kt & 1;
        if (kt + 1 < NK) {
            load_stage(s ^ 1, kt + 1);
            __pipeline_wait_prior(1);
        } else {
            __pipeline_wait_prior(0);
        }
        __syncthreads();

        __nv_bfloat16* sb = sA + s * STGE;
        __nv_bfloat16* sB = sb + A_ELEMS;
        #pragma unroll
        for (int kk = 0; kk < 32; kk += 16) {
            wmma::fragment<wmma::matrix_b, 16, 16, 16, __nv_bfloat16, wmma::row_major> fbh[2], fbl[2];
            #pragma unroll
            for (int j = 0; j < 2; j++) {
                int n0 = wn*32 + j*16;
                wmma::load_matrix_sync(fbh[j], sB + kk*LDB + n0, LDB);
                wmma::load_matrix_sync(fbl[j], sB + (32 + kk)*LDB + n0, LDB);
            }
            #pragma unroll
            for (int i = 0; i < 4; i++) {
                wmma::fragment<wmma::matrix_a, 16, 16, 16, __nv_bfloat16, wmma::row_major> fah, fal;
                int m0 = wm*64 + i*16;
                wmma::load_matrix_sync(fah, sb + m0*LDA + kk, LDA);
                wmma::load_matrix_sync(fal, sb + (256 + m0)*LDA + kk, LDA);
                #pragma unroll
                for (int j = 0; j < 2; j++) {
                    wmma::mma_sync(acc[i][j], fah, fbh[j], acc[i][j]);
                    wmma::mma_sync(acc[i][j], fah, fbl[j], acc[i][j]);
                    wmma::mma_sync(acc[i][j], fal, fbh[j], acc[i][j]);
                }
            }
        }
        __syncthreads();
    }

    // epilogue: park accumulators in smem (256x128 fp32 = 128KB), fused bias/residual
    float* sOut = (float*)smem;
    #pragma unroll
    for (int i = 0; i < 4; i++)
        #pragma unroll
        for (int j = 0; j < 2; j++)
            wmma::store_matrix_sync(sOut + (wm*64 + i*16)*128 + (wn*32 + j*16),
                                    acc[i][j], 128, wmma::mem_row_major);
    __syncthreads();

    int b = bn >> 12;
    int pin = bn & 4095;
    int r0 = tid >> 5;            // 0..15
    int c4 = (tid & 31) * 4;      // 0..124
    #pragma unroll
    for (int i = 0; i < 16; i++) {
        int o = r0 + i*16;        // output channel 0..255
        float4 v = *(float4*)(sOut + o*128 + c4);
        float bs = bias[o];
        v.x += bs; v.y += bs; v.z += bs; v.w += bs;
        size_t off = ((size_t)(b*256 + o))*4096 + pin + c4;
        if (res) {
            float4 rr = *(const float4*)(res + off);
            v.x += rr.x; v.y += rr.y; v.z += rr.z; v.w += rr.w;
        }
        *(float4*)(out + off) = v;
    }
}

// ---------------- launch ----------------
extern "C" void kernel_launch(void* const* d_in, const int* in_sizes, int n_in,
                              void* d_out, int out_size) {
    const float* x    = (const float*)d_in[0];
    const float* gn1g = (const float*)d_in[1];
    const float* gn1b = (const float*)d_in[2];
    const float* dw1  = (const float*)d_in[3];
    const float* pw1  = (const float*)d_in[4];
    const float* pwb1 = (const float*)d_in[5];
    const float* w1   = (const float*)d_in[6];
    const float* b1   = (const float*)d_in[7];
    const float* gn2g = (const float*)d_in[8];
    const float* gn2b = (const float*)d_in[9];
    const float* dw2  = (const float*)d_in[10];
    const float* pw2  = (const float*)d_in[11];
    const float* pwb2 = (const float*)d_in[12];
    const float* w2   = (const float*)d_in[13];
    const float* b2   = (const float*)d_in[14];
    float* out = (float*)d_out;

    cudaFuncSetAttribute(gemm_wmma_kernel, cudaFuncAttributeMaxDynamicSharedMemorySize, SMEM_GEMM);

    // stage 1
    gn_relu_kernel<<<128, 256>>>(x, gn1g, gn1b);
    dw_conv_kernel<<<BB*CC, 256>>>(dw1);
    pw_kernel<<<64, 256>>>(pw1, pwb1);
    im2col_bf16_kernel<<<576, 256>>>();
    repack_w_kernel<<<CC*CK/256, 256>>>(w1);
    gemm_wmma_kernel<<<128, 512, SMEM_GEMM>>>(b1, nullptr, nullptr);

    // stage 2
    gn_relu_kernel<<<128, 256>>>(nullptr, gn2g, gn2b);
    dw_conv_kernel<<<BB*CC, 256>>>(dw2);
    pw_kernel<<<64, 256>>>(pw2, pwb2);
    im2col_bf16_kernel<<<576, 256>>>();
    repack_w_kernel<<<CC*CK/256, 256>>>(w2);
    gemm_wmma_kernel<<<128, 512, SMEM_GEMM>>>(b2, x, out);
}

// round 11
// speedup vs baseline: 3.5976x; 1.6754x over previous
#include <cuda_runtime.h>
#include <cuda_bf16.h>
#include <cuda_fp16.h>
#include <mma.h>
#include <cuda_pipeline.h>
#include <math.h>
#include <stdint.h>

using namespace nvcuda;

#define BB 4
#define CC 256
#define HW 4096
#define CK 2304
#define CPG 8
#define NPIX 16384
#define LDA 72                           /* 64 + 8 pad */
#define LDB 136                          /* 128 + 8 pad */
#define A_ELEMS (256*LDA)                /* 18432 */
#define STGE (A_ELEMS + 64*LDB)          /* 27136 halves per stage */
#define SMEM_GEMM 131072                 /* epilogue 256x128 fp32; > 2 stages (108544B) */

// ---------------- scratch (device globals; no allocations) ----------------
__device__ __align__(128) float g_h  [(size_t)BB*CC*HW];
__device__ __align__(128) float g_f  [(size_t)BB*CC*HW];
__device__ __align__(128) float g_off[(size_t)BB*18*HW];
__device__ __align__(128) float g_h2 [(size_t)BB*CC*HW];
__device__ __align__(128) __half g_col[(size_t)CK*NPIX];   // [K][pixels], fp16
__device__ __align__(128) __half g_w  [(size_t)CC*CK];     // [O][k*256+c], fp16

// ---------------- GroupNorm + ReLU (in: x or g_h2; out: g_h) ----------------
__global__ void gn_relu_kernel(const float* __restrict__ inp,
                               const float* __restrict__ gamma,
                               const float* __restrict__ beta) {
    const float* in = inp ? inp : (const float*)g_h2;
    int b = blockIdx.x >> 5, g = blockIdx.x & 31;
    size_t base = ((size_t)b*CC + g*CPG) * HW;
    const float4* p4 = (const float4*)(in + base);
    const int N4 = CPG*HW/4;
    float s = 0.f, s2 = 0.f;
    for (int i = threadIdx.x; i < N4; i += 256) {
        float4 v = p4[i];
        s  += v.x + v.y + v.z + v.w;
        s2 += v.x*v.x + v.y*v.y + v.z*v.z + v.w*v.w;
    }
    #pragma unroll
    for (int o = 16; o; o >>= 1) {
        s  += __shfl_xor_sync(0xffffffffu, s,  o);
        s2 += __shfl_xor_sync(0xffffffffu, s2, o);
    }
    __shared__ float sh[16];
    __shared__ float stats[2];
    int wid = threadIdx.x >> 5, lane = threadIdx.x & 31;
    if (lane == 0) { sh[wid] = s; sh[8 + wid] = s2; }
    __syncthreads();
    if (threadIdx.x == 0) {
        float ts = 0.f, ts2 = 0.f;
        #pragma unroll
        for (int i = 0; i < 8; i++) { ts += sh[i]; ts2 += sh[8+i]; }
        const float invN = 1.f / (float)(CPG*HW);
        float mean = ts * invN;
        float var  = ts2 * invN - mean*mean;
        stats[0] = mean;
        stats[1] = rsqrtf(var + 1e-5f);
    }
    __syncthreads();
    float mean = stats[0], inv = stats[1];
    float4* o4 = (float4*)(g_h + base);
    for (int i = threadIdx.x; i < N4; i += 256) {
        int c = g*CPG + (i >> 10);
        float ga = gamma[c] * inv;
        float be = beta[c] - mean * ga;
        float4 v = p4[i];
        v.x = fmaxf(fmaf(v.x, ga, be), 0.f);
        v.y = fmaxf(fmaf(v.y, ga, be), 0.f);
        v.z = fmaxf(fmaf(v.z, ga, be), 0.f);
        v.w = fmaxf(fmaf(v.w, ga, be), 0.f);
        o4[i] = v;
    }
}

// ---------------- Depthwise 7x7 SAME (g_h -> g_f) ----------------
__global__ void dw_conv_kernel(const float* __restrict__ wts) {
    int bc = blockIdx.x;
    int c = bc & (CC - 1);
    const float* p = g_h + (size_t)bc * HW;
    __shared__ float tile[70*70];
    __shared__ float wk[49];
    if (threadIdx.x < 49) wk[threadIdx.x] = wts[c*49 + threadIdx.x];
    for (int i = threadIdx.x; i < 70*70; i += 256) {
        int ty = i / 70 - 3, tx = i % 70 - 3;
        tile[i] = (ty >= 0 && ty < 64 && tx >= 0 && tx < 64) ? p[ty*64 + tx] : 0.f;
    }
    __syncthreads();
    int xg = (threadIdx.x & 15) * 4;
    int yb = threadIdx.x >> 4;
    #pragma unroll
    for (int it = 0; it < 4; it++) {
        int oy = it*16 + yb;
        float a0 = 0.f, a1 = 0.f, a2 = 0.f, a3 = 0.f;
        #pragma unroll
        for (int dy = 0; dy < 7; dy++) {
            const float* r = &tile[(oy+dy)*70 + xg];
            #pragma unroll
            for (int dx = 0; dx < 7; dx++) {
                float wv = wk[dy*7 + dx];
                a0 = fmaf(r[dx+0], wv, a0);
                a1 = fmaf(r[dx+1], wv, a1);
                a2 = fmaf(r[dx+2], wv, a2);
                a3 = fmaf(r[dx+3], wv, a3);
            }
        }
        float4 o4 = make_float4(a0, a1, a2, a3);
        *(float4*)&g_f[(size_t)bc*HW + oy*64 + xg] = o4;
    }
}

// ---------------- Pointwise 1x1 + bias (g_f -> g_off) ----------------
__global__ void pw_kernel(const float* __restrict__ pw,
                          const float* __restrict__ pwb) {
    int b = blockIdx.x >> 4;
    int p = (blockIdx.x & 15) * 256 + threadIdx.x;
    __shared__ float wsh[18*256];
    for (int i = threadIdx.x; i < 18*256; i += 256) wsh[i] = pw[i];
    __syncthreads();
    float acc[18];
    #pragma unroll
    for (int o = 0; o < 18; o++) acc[o] = 0.f;
    const float* fb = g_f + (size_t)b*CC*HW + p;
    for (int c = 0; c < CC; c++) {
        float v = fb[(size_t)c*HW];
        #pragma unroll
        for (int o = 0; o < 18; o++) acc[o] = fmaf(v, wsh[o*256 + c], acc[o]);
    }
    #pragma unroll
    for (int o = 0; o < 18; o++)
        g_off[((size_t)b*18 + o)*HW + p] = acc[o] + pwb[o];
}

// ---------------- im2col bilinear -> fp16, layout [k*256+c][b*HW+p] ----------------
// grid = 576: pc(8) x ch(2) x k(9) x b(4); 256 threads; each thread = 2 adjacent pixels, 128 ch
__device__ __forceinline__ unsigned int pack_h2(__half a, __half b) {
    return (unsigned int)__half_as_ushort(a) |
           ((unsigned int)__half_as_ushort(b) << 16);
}
__global__ void im2col_f16_kernel() {
    int blk = blockIdx.x;
    int pc = blk & 7;
    int t2 = blk >> 3;
    int ch = t2 & 1;
    t2 >>= 1;
    int k = t2 % 9;
    int b = t2 / 9;
    int p0 = pc*512 + threadIdx.x*2;

    float ky = (float)(k/3 - 1), kx = (float)(k%3 - 1);
    int idx[2][4];
    float wgt[2][4];
    #pragma unroll
    for (int e = 0; e < 2; e++) {
        int p = p0 + e;
        int yi = p >> 6, xi = p & 63;
        float offy = g_off[((size_t)b*18 + 2*k    )*HW + p];
        float offx = g_off[((size_t)b*18 + 2*k + 1)*HW + p];
        float py = (float)yi + ky + offy;
        float px = (float)xi + kx + offx;
        float y0f = floorf(py), x0f = floorf(px);
        float wy1 = py - y0f, wx1 = px - x0f;
        float wy0 = 1.f - wy1, wx0 = 1.f - wx1;
        float y1f = y0f + 1.f, x1f = x0f + 1.f;
        bool vy0 = (y0f >= 0.f) && (y0f <= 63.f);
        bool vy1 = (y1f >= 0.f) && (y1f <= 63.f);
        bool vx0 = (x0f >= 0.f) && (x0f <= 63.f);
        bool vx1 = (x1f >= 0.f) && (x1f <= 63.f);
        wgt[e][0] = (vy0 && vx0) ? wy0*wx0 : 0.f;
        wgt[e][1] = (vy0 && vx1) ? wy0*wx1 : 0.f;
        wgt[e][2] = (vy1 && vx0) ? wy1*wx0 : 0.f;
        wgt[e][3] = (vy1 && vx1) ? wy1*wx1 : 0.f;
        int yc0 = min(max((int)y0f, 0), 63);
        int yc1 = min(max((int)y1f, 0), 63);
        int xc0 = min(max((int)x0f, 0), 63);
        int xc1 = min(max((int)x1f, 0), 63);
        idx[e][0] = yc0*64 + xc0;
        idx[e][1] = yc0*64 + xc1;
        idx[e][2] = yc1*64 + xc0;
        idx[e][3] = yc1*64 + xc1;
    }

    const float* xb = g_h + (size_t)b*CC*HW;
    size_t gcol = (size_t)b*HW + p0;   // pixel coordinate (even -> 4B aligned)
    int c0 = ch*128;
    #pragma unroll 4
    for (int c = c0; c < c0 + 128; c++) {
        const float* pl = xb + (size_t)c*HW;
        float v[2];
        #pragma unroll
        for (int e = 0; e < 2; e++) {
            float t = wgt[e][0]*pl[idx[e][0]];
            t = fmaf(wgt[e][1], pl[idx[e][1]], t);
            t = fmaf(wgt[e][2], pl[idx[e][2]], t);
            t = fmaf(wgt[e][3], pl[idx[e][3]], t);
            v[e] = t;
        }
        size_t row = (size_t)(k*256 + c) * NPIX + gcol;
        *(unsigned int*)(g_col + row) = pack_h2(__float2half(v[0]), __float2half(v[1]));
    }
}

// ---------------- weight repack: [O][c*9+k] fp32 -> [O][k*256+c] fp16 ----------------
__global__ void repack_w_kernel(const float* __restrict__ w) {
    int idx = blockIdx.x*256 + threadIdx.x;
    int o = idx / CK;
    int rem = idx - o*CK;
    int c = rem / 9;
    int k = rem - c*9;
    g_w[o*CK + k*256 + c] = __float2half(w[idx]);
}

// ---------------- WMMA fp16 GEMM ----------------
// C[o,p] = sum_ck W[o,ck]*col[ck,p]; BM=256 (all M), BN=128, BK=64
// 512 threads = 16 warps (4x4); warp tile 64x32 -> acc[4][2]
// smem stage (fp16): 256 A-rows (ld=72), 64 B-rows (ld=136)
__global__ void __launch_bounds__(512, 1) gemm_wmma_kernel(
        const float* __restrict__ bias,
        const float* __restrict__ res,     // null or x (residual)
        float* __restrict__ outp) {        // null -> write g_h2
    extern __shared__ __align__(16) char smem[];
    __half* sA = (__half*)smem;
    int tid = threadIdx.x;
    int warp = tid >> 5;
    int wm = warp & 3;      // 0..3 -> 64-row tiles
    int wn = warp >> 2;     // 0..3 -> 32-col tiles
    int bn = blockIdx.x * 128;
    float* out = outp ? outp : (float*)g_h2;

    wmma::fragment<wmma::accumulator, 16, 16, 16, float> acc[4][2];
    #pragma unroll
    for (int i = 0; i < 4; i++)
        #pragma unroll
        for (int j = 0; j < 2; j++)
            wmma::fill_fragment(acc[i][j], 0.f);

    // stage loader: 3072 16B-chunks (2048 A + 1024 B), 6 per thread
    auto load_stage = [&](int buf, int kt) {
        __half* sb = sA + buf * STGE;
        int ko = kt * 64;
        #pragma unroll
        for (int u = 0; u < 6; u++) {
            int i = tid + u*512;
            const __half* src;
            __half* dst;
            if (i < 2048) {
                int row = i >> 3;            // 0..255
                int c8 = (i & 7) * 8;        // 0..56
                src = g_w + (size_t)row*CK + ko + c8;
                dst = sb + row*LDA + c8;
            } else {
                int j = i - 2048;
                int row = j >> 4;            // 0..63 (k within chunk)
                int e8 = (j & 15) * 8;       // 0..120
                src = g_col + (size_t)(ko + row)*NPIX + bn + e8;
                dst = sb + A_ELEMS + row*LDB + e8;
            }
            __pipeline_memcpy_async(dst, src, 16);
        }
        __pipeline_commit();
    };

    load_stage(0, 0);

    const int NK = CK / 64;    // 36
    for (int kt = 0; kt < NK; kt++) {
        int s = kt & 1;
        if (kt + 1 < NK) {
            load_stage(s ^ 1, kt + 1);
            __pipeline_wait_prior(1);
        } else {
            __pipeline_wait_prior(0);
        }
        __syncthreads();

        __half* sb = sA + s * STGE;
        __half* sB = sb + A_ELEMS;
        #pragma unroll
        for (int kk = 0; kk < 64; kk += 16) {
            wmma::fragment<wmma::matrix_b, 16, 16, 16, __half, wmma::row_major> fb[2];
            #pragma unroll
            for (int j = 0; j < 2; j++)
                wmma::load_matrix_sync(fb[j], sB + kk*LDB + wn*32 + j*16, LDB);
            #pragma unroll
            for (int i = 0; i < 4; i++) {
                wmma::fragment<wmma::matrix_a, 16, 16, 16, __half, wmma::row_major> fa;
                wmma::load_matrix_sync(fa, sb + (wm*64 + i*16)*LDA + kk, LDA);
                #pragma unroll
                for (int j = 0; j < 2; j++)
                    wmma::mma_sync(acc[i][j], fa, fb[j], acc[i][j]);
            }
        }
        __syncthreads();
    }

    // epilogue: park accumulators in smem (256x128 fp32 = 128KB), fused bias/residual
    float* sOut = (float*)smem;
    #pragma unroll
    for (int i = 0; i < 4; i++)
        #pragma unroll
        for (int j = 0; j < 2; j++)
            wmma::store_matrix_sync(sOut + (wm*64 + i*16)*128 + (wn*32 + j*16),
                                    acc[i][j], 128, wmma::mem_row_major);
    __syncthreads();

    int b = bn >> 12;
    int pin = bn & 4095;
    int r0 = tid >> 5;            // 0..15
    int c4 = (tid & 31) * 4;      // 0..124
    #pragma unroll
    for (int i = 0; i < 16; i++) {
        int o = r0 + i*16;        // output channel 0..255
        float4 v = *(float4*)(sOut + o*128 + c4);
        float bs = bias[o];
        v.x += bs; v.y += bs; v.z += bs; v.w += bs;
        size_t off = ((size_t)(b*256 + o))*4096 + pin + c4;
        if (res) {
            float4 rr = *(const float4*)(res + off);
            v.x += rr.x; v.y += rr.y; v.z += rr.z; v.w += rr.w;
        }
        *(float4*)(out + off) = v;
    }
}

// ---------------- launch ----------------
extern "C" void kernel_launch(void* const* d_in, const int* in_sizes, int n_in,
                              void* d_out, int out_size) {
    const float* x    = (const float*)d_in[0];
    const float* gn1g = (const float*)d_in[1];
    const float* gn1b = (const float*)d_in[2];
    const float* dw1  = (const float*)d_in[3];
    const float* pw1  = (const float*)d_in[4];
    const float* pwb1 = (const float*)d_in[5];
    const float* w1   = (const float*)d_in[6];
    const float* b1   = (const float*)d_in[7];
    const float* gn2g = (const float*)d_in[8];
    const float* gn2b = (const float*)d_in[9];
    const float* dw2  = (const float*)d_in[10];
    const float* pw2  = (const float*)d_in[11];
    const float* pwb2 = (const float*)d_in[12];
    const float* w2   = (const float*)d_in[13];
    const float* b2   = (const float*)d_in[14];
    float* out = (float*)d_out;

    cudaFuncSetAttribute(gemm_wmma_kernel, cudaFuncAttributeMaxDynamicSharedMemorySize, SMEM_GEMM);

    // stage 1
    gn_relu_kernel<<<128, 256>>>(x, gn1g, gn1b);
    dw_conv_kernel<<<BB*CC, 256>>>(dw1);
    pw_kernel<<<64, 256>>>(pw1, pwb1);
    im2col_f16_kernel<<<576, 256>>>();
    repack_w_kernel<<<CC*CK/256, 256>>>(w1);
    gemm_wmma_kernel<<<128, 512, SMEM_GEMM>>>(b1, nullptr, nullptr);

    // stage 2
    gn_relu_kernel<<<128, 256>>>(nullptr, gn2g, gn2b);
    dw_conv_kernel<<<BB*CC, 256>>>(dw2);
    pw_kernel<<<64, 256>>>(pw2, pwb2);
    im2col_f16_kernel<<<576, 256>>>();
    repack_w_kernel<<<CC*CK/256, 256>>>(w2);
    gemm_wmma_kernel<<<128, 512, SMEM_GEMM>>>(b2, x, out);
}